// round 14
// baseline (speedup 1.0000x reference)
#include <cuda_runtime.h>
#include <cuda_fp16.h>
#include <cstdint>

// GCN 2-layer, CSR two-phase aggregation, sm_100a.
// f32x2 packed GEMM (1 row/thread, unroll-limited for occupancy), Hs fp16,
// CSR agg with x8 MLP. Prep = R11 config (4-edge hist/fill + init).

#define N_NODES 100000
#define N_EDGES 1600000
#define D 64
#define FIXS 33554432.0f          // 2^25 fixed-point scale for weight sums
#define FIXR (1.0f / 33554432.0f)

__device__ unsigned long long g_pk[N_NODES];  // (cnt << 32) | fixed_weight_sum
__device__ float g_dis[N_NODES];        // rsqrt(degree)
__device__ int   g_cnt[N_NODES];        // in-degree (edges only)
__device__ int   g_row[N_NODES];        // CSR row start (bump-allocated)
__device__ int   g_total;               // bump allocator
__device__ int   g_pos[N_EDGES];        // within-bin slot (from hist atomic)
__device__ int2  g_bins[N_EDGES];       // (src, w-as-int), dst-binned
__device__ uint2 g_h[N_NODES * 16];     // Hs fp16: 64 half = 16 uint2 per node
__device__ float g_agg[N_NODES * D];    // layer-1 output (fp32)

// ---------------------------------------------------------------------------
// packed f32x2 helpers (sm_100+)
// ---------------------------------------------------------------------------
__device__ __forceinline__ unsigned long long bcast2(float x) {
    unsigned long long r;
    asm("mov.b64 %0, {%1, %1};" : "=l"(r) : "f"(x));
    return r;
}
__device__ __forceinline__ void fma2(unsigned long long& d,
                                     unsigned long long a,
                                     unsigned long long b) {
    asm("fma.rn.f32x2 %0, %1, %2, %0;" : "+l"(d) : "l"(a), "l"(b));
}
__device__ __forceinline__ float2 unpack2(unsigned long long v) {
    float2 f;
    asm("mov.b64 {%0, %1}, %2;" : "=f"(f.x), "=f"(f.y) : "l"(v));
    return f;
}

// ---------------------------------------------------------------------------
__global__ void k_init() {
    int i = blockIdx.x * blockDim.x + threadIdx.x;
    if (i < N_NODES) g_pk[i] = 0ULL;
    if (i == 0) g_total = 0;
}

// one packed 64-bit atomic per edge: count (hi) + fixed-point weight sum (lo)
__global__ void k_hist(const int* __restrict__ dst,
                       const float* __restrict__ w) {
    int t = blockIdx.x * blockDim.x + threadIdx.x;
    if (t >= N_EDGES / 4) return;
    int4   dv = ((const int4*)dst)[t];
    float4 wv = ((const float4*)w)[t];
    unsigned long long a0 = (1ULL << 32) | (unsigned)__float2uint_rn(wv.x * FIXS);
    unsigned long long a1 = (1ULL << 32) | (unsigned)__float2uint_rn(wv.y * FIXS);
    unsigned long long a2 = (1ULL << 32) | (unsigned)__float2uint_rn(wv.z * FIXS);
    unsigned long long a3 = (1ULL << 32) | (unsigned)__float2uint_rn(wv.w * FIXS);
    int p0 = (int)(atomicAdd(&g_pk[dv.x], a0) >> 32);
    int p1 = (int)(atomicAdd(&g_pk[dv.y], a1) >> 32);
    int p2 = (int)(atomicAdd(&g_pk[dv.z], a2) >> 32);
    int p3 = (int)(atomicAdd(&g_pk[dv.w], a3) >> 32);
    ((int4*)g_pos)[t] = make_int4(p0, p1, p2, p3);
}

__global__ void k_alloc() {
    int i = blockIdx.x * blockDim.x + threadIdx.x;
    if (i >= N_NODES) return;
    unsigned long long pk = g_pk[i];
    int cnt = (int)(pk >> 32);
    float deg = 1.0f + (float)(unsigned)(pk & 0xFFFFFFFFULL) * FIXR;
    g_dis[i] = rsqrtf(deg);
    g_cnt[i] = cnt;
    g_row[i] = atomicAdd(&g_total, cnt);
}

// fill bins: payload (src, raw w); one row[dst] gather, no dis gathers
__global__ void k_fill(const int* __restrict__ src,
                       const int* __restrict__ dst,
                       const float* __restrict__ w) {
    int t = blockIdx.x * blockDim.x + threadIdx.x;
    if (t >= N_EDGES / 4) return;
    int4   sv = ((const int4*)src)[t];
    int4   dv = ((const int4*)dst)[t];
    int4   pv = ((const int4*)g_pos)[t];
    float4 wv = ((const float4*)w)[t];
    int r0 = g_row[dv.x], r1 = g_row[dv.y], r2 = g_row[dv.z], r3 = g_row[dv.w];
    g_bins[r0 + pv.x] = make_int2(sv.x, __float_as_int(wv.x));
    g_bins[r1 + pv.y] = make_int2(sv.y, __float_as_int(wv.y));
    g_bins[r2 + pv.z] = make_int2(sv.z, __float_as_int(wv.z));
    g_bins[r3 + pv.w] = make_int2(sv.w, __float_as_int(wv.w));
}

// ---------------------------------------------------------------------------
// dense 64x64 GEMM, f32x2 packed math, 1 row/thread, k-loop unroll-limited
// to keep registers low (occupancy), fp16 output:
//   Hs[row] = half( dis[row] * (X[row] @ W) )
// ---------------------------------------------------------------------------
__global__ void __launch_bounds__(128) k_gemm(const float* __restrict__ X,
                                              const float* __restrict__ W,
                                              uint2* __restrict__ H) {
    __shared__ ulonglong2 WsU[1024];          // 64x64 floats = 16KB
    float* Ws = (float*)WsU;
    int tid = threadIdx.x;
    {
        const float4* W4 = (const float4*)W;
        float4* Ws4 = (float4*)Ws;
#pragma unroll
        for (int i = 0; i < 8; ++i) Ws4[tid + i * 128] = W4[tid + i * 128];
    }
    __syncthreads();

    int row = blockIdx.x * 128 + tid;
    if (row >= N_NODES) return;

    float di = g_dis[row];
    const float4* x4 = (const float4*)(X + (size_t)row * D);

#pragma unroll 1
    for (int jc = 0; jc < 4; ++jc) {            // 16 output channels per chunk
        unsigned long long a[8];
#pragma unroll
        for (int j = 0; j < 8; ++j) a[j] = 0ULL;

#pragma unroll 4
        for (int k4 = 0; k4 < 16; ++k4) {       // limit X regs in flight
            float4 xv = x4[k4];                  // L1-hot after jc=0
            float xs[4] = {xv.x, xv.y, xv.z, xv.w};
#pragma unroll
            for (int kk = 0; kk < 4; ++kk) {
                int k = k4 * 4 + kk;
                unsigned long long xb = bcast2(xs[kk]);
                const ulonglong2* wrow =
                    (const ulonglong2*)(Ws + k * D + jc * 16);
#pragma unroll
                for (int q = 0; q < 4; ++q) {
                    ulonglong2 wp = wrow[q];     // warp-uniform LDS.128
                    fma2(a[q * 2 + 0], wp.x, xb);
                    fma2(a[q * 2 + 1], wp.y, xb);
                }
            }
        }
#pragma unroll
        for (int q = 0; q < 4; ++q) {
            float2 f0 = unpack2(a[q * 2 + 0]);
            float2 f1 = unpack2(a[q * 2 + 1]);
            __half2 h0 = __floats2half2_rn(f0.x * di, f0.y * di);
            __half2 h1 = __floats2half2_rn(f1.x * di, f1.y * di);
            H[(size_t)row * 16 + jc * 4 + q] =
                make_uint2(*(unsigned*)&h0, *(unsigned*)&h1);
        }
    }
}

// ---------------------------------------------------------------------------
// CSR aggregate: 16 lanes per node; lane owns 4 channels (uint2 = 2 half2).
// fp32 accumulation; fused self-loop, dis scale, ReLU. x8 unroll (MLP=8).
// ---------------------------------------------------------------------------
__device__ __forceinline__ void acc_h4(float4& acc, uint2 v, float nm) {
    float2 f0 = __half22float2(*(__half2*)&v.x);
    float2 f1 = __half22float2(*(__half2*)&v.y);
    acc.x = fmaf(nm, f0.x, acc.x); acc.y = fmaf(nm, f0.y, acc.y);
    acc.z = fmaf(nm, f1.x, acc.z); acc.w = fmaf(nm, f1.y, acc.w);
}

__global__ void __launch_bounds__(256) k_agg(const uint2* __restrict__ H,
                                             float* __restrict__ A) {
    int idx = blockIdx.x * 256 + threadIdx.x;
    int n = idx >> 4;
    if (n >= N_NODES) return;
    int l = idx & 15;

    int e   = g_row[n];
    int end = e + g_cnt[n];

    float4 acc;
    {   // self-loop term Hs[n]
        uint2 sv = H[(size_t)n * 16 + l];
        float2 f0 = __half22float2(*(__half2*)&sv.x);
        float2 f1 = __half22float2(*(__half2*)&sv.y);
        acc = make_float4(f0.x, f0.y, f1.x, f1.y);
    }

    for (; e + 8 <= end; e += 8) {
        int2 p[8];
#pragma unroll
        for (int j = 0; j < 8; ++j) p[j] = g_bins[e + j];
        uint2 v[8];
#pragma unroll
        for (int j = 0; j < 8; ++j) v[j] = H[(size_t)p[j].x * 16 + l];
#pragma unroll
        for (int j = 0; j < 8; ++j) acc_h4(acc, v[j], __int_as_float(p[j].y));
    }
    if (e + 4 <= end) {
        int2 p[4];
#pragma unroll
        for (int j = 0; j < 4; ++j) p[j] = g_bins[e + j];
        uint2 v[4];
#pragma unroll
        for (int j = 0; j < 4; ++j) v[j] = H[(size_t)p[j].x * 16 + l];
#pragma unroll
        for (int j = 0; j < 4; ++j) acc_h4(acc, v[j], __int_as_float(p[j].y));
        e += 4;
    }
    for (; e < end; ++e) {
        int2 p = g_bins[e];
        uint2 v = H[(size_t)p.x * 16 + l];
        acc_h4(acc, v, __int_as_float(p.y));
    }

    float di = g_dis[n];
    acc.x = fmaxf(acc.x * di, 0.f); acc.y = fmaxf(acc.y * di, 0.f);
    acc.z = fmaxf(acc.z * di, 0.f); acc.w = fmaxf(acc.w * di, 0.f);
    ((float4*)A)[(size_t)n * 16 + l] = acc;
}

// ---------------------------------------------------------------------------
extern "C" void kernel_launch(void* const* d_in, const int* in_sizes, int n_in,
                              void* d_out, int out_size) {
    const float* x   = (const float*)d_in[0];
    const int*   ei  = (const int*)d_in[1];     // int32 (JAX x64 disabled)
    const float* w   = (const float*)d_in[2];
    const float* W0  = (const float*)d_in[3];
    const float* W1  = (const float*)d_in[4];
    float* out = (float*)d_out;

    const int* src = ei;
    const int* dst = ei + N_EDGES;

    uint2* p_h;
    float* p_agg;
    cudaGetSymbolAddress((void**)&p_h, g_h);
    cudaGetSymbolAddress((void**)&p_agg, g_agg);

    const int TB = 256;
    int gN    = (N_NODES + TB - 1) / TB;
    int gE4   = (N_EDGES / 4 + TB - 1) / TB;
    int gAgg  = (N_NODES * 16 + TB - 1) / TB;
    int gGemm = (N_NODES + 127) / 128;          // 1 row/thread, 128 thr

    // prep
    k_init<<<gN, TB>>>();
    k_hist<<<gE4, TB>>>(dst, w);
    k_alloc<<<gN, TB>>>();
    k_fill<<<gE4, TB>>>(src, dst, w);

    // layer 1
    k_gemm<<<gGemm, 128>>>(x, W0, p_h);
    k_agg<<<gAgg, TB>>>(p_h, p_agg);

    // layer 2
    k_gemm<<<gGemm, 128>>>(p_agg, W1, p_h);
    k_agg<<<gAgg, TB>>>(p_h, out);
}

// round 15
// speedup vs baseline: 1.1475x; 1.1475x over previous
#include <cuda_runtime.h>
#include <cuda_fp16.h>
#include <cstdint>

// GCN 2-layer, CSR two-phase aggregation, sm_100a.
// GEMM: f32x2 packed, 1 row/thread, 2 passes of 32 output channels
// (single k-sweep per pass; ~80 regs for occupancy). Hs fp16. Agg x8 MLP.
// Prep = R11 config (4-edge hist/fill + init).

#define N_NODES 100000
#define N_EDGES 1600000
#define D 64
#define FIXS 33554432.0f          // 2^25 fixed-point scale for weight sums
#define FIXR (1.0f / 33554432.0f)

__device__ unsigned long long g_pk[N_NODES];  // (cnt << 32) | fixed_weight_sum
__device__ float g_dis[N_NODES];        // rsqrt(degree)
__device__ int   g_cnt[N_NODES];        // in-degree (edges only)
__device__ int   g_row[N_NODES];        // CSR row start (bump-allocated)
__device__ int   g_total;               // bump allocator
__device__ int   g_pos[N_EDGES];        // within-bin slot (from hist atomic)
__device__ int2  g_bins[N_EDGES];       // (src, w-as-int), dst-binned
__device__ uint2 g_h[N_NODES * 16];     // Hs fp16: 64 half = 16 uint2 per node
__device__ float g_agg[N_NODES * D];    // layer-1 output (fp32)

// ---------------------------------------------------------------------------
// packed f32x2 helpers (sm_100+)
// ---------------------------------------------------------------------------
__device__ __forceinline__ unsigned long long bcast2(float x) {
    unsigned long long r;
    asm("mov.b64 %0, {%1, %1};" : "=l"(r) : "f"(x));
    return r;
}
__device__ __forceinline__ void fma2(unsigned long long& d,
                                     unsigned long long a,
                                     unsigned long long b) {
    asm("fma.rn.f32x2 %0, %1, %2, %0;" : "+l"(d) : "l"(a), "l"(b));
}
__device__ __forceinline__ float2 unpack2(unsigned long long v) {
    float2 f;
    asm("mov.b64 {%0, %1}, %2;" : "=f"(f.x), "=f"(f.y) : "l"(v));
    return f;
}

// ---------------------------------------------------------------------------
__global__ void k_init() {
    int i = blockIdx.x * blockDim.x + threadIdx.x;
    if (i < N_NODES) g_pk[i] = 0ULL;
    if (i == 0) g_total = 0;
}

// one packed 64-bit atomic per edge: count (hi) + fixed-point weight sum (lo)
__global__ void k_hist(const int* __restrict__ dst,
                       const float* __restrict__ w) {
    int t = blockIdx.x * blockDim.x + threadIdx.x;
    if (t >= N_EDGES / 4) return;
    int4   dv = ((const int4*)dst)[t];
    float4 wv = ((const float4*)w)[t];
    unsigned long long a0 = (1ULL << 32) | (unsigned)__float2uint_rn(wv.x * FIXS);
    unsigned long long a1 = (1ULL << 32) | (unsigned)__float2uint_rn(wv.y * FIXS);
    unsigned long long a2 = (1ULL << 32) | (unsigned)__float2uint_rn(wv.z * FIXS);
    unsigned long long a3 = (1ULL << 32) | (unsigned)__float2uint_rn(wv.w * FIXS);
    int p0 = (int)(atomicAdd(&g_pk[dv.x], a0) >> 32);
    int p1 = (int)(atomicAdd(&g_pk[dv.y], a1) >> 32);
    int p2 = (int)(atomicAdd(&g_pk[dv.z], a2) >> 32);
    int p3 = (int)(atomicAdd(&g_pk[dv.w], a3) >> 32);
    ((int4*)g_pos)[t] = make_int4(p0, p1, p2, p3);
}

__global__ void k_alloc() {
    int i = blockIdx.x * blockDim.x + threadIdx.x;
    if (i >= N_NODES) return;
    unsigned long long pk = g_pk[i];
    int cnt = (int)(pk >> 32);
    float deg = 1.0f + (float)(unsigned)(pk & 0xFFFFFFFFULL) * FIXR;
    g_dis[i] = rsqrtf(deg);
    g_cnt[i] = cnt;
    g_row[i] = atomicAdd(&g_total, cnt);
}

// fill bins: payload (src, raw w); one row[dst] gather, no dis gathers
__global__ void k_fill(const int* __restrict__ src,
                       const int* __restrict__ dst,
                       const float* __restrict__ w) {
    int t = blockIdx.x * blockDim.x + threadIdx.x;
    if (t >= N_EDGES / 4) return;
    int4   sv = ((const int4*)src)[t];
    int4   dv = ((const int4*)dst)[t];
    int4   pv = ((const int4*)g_pos)[t];
    float4 wv = ((const float4*)w)[t];
    int r0 = g_row[dv.x], r1 = g_row[dv.y], r2 = g_row[dv.z], r3 = g_row[dv.w];
    g_bins[r0 + pv.x] = make_int2(sv.x, __float_as_int(wv.x));
    g_bins[r1 + pv.y] = make_int2(sv.y, __float_as_int(wv.y));
    g_bins[r2 + pv.z] = make_int2(sv.z, __float_as_int(wv.z));
    g_bins[r3 + pv.w] = make_int2(sv.w, __float_as_int(wv.w));
}

// ---------------------------------------------------------------------------
// dense 64x64 GEMM, f32x2 packed math, 1 row/thread.
// 2 passes of 32 output channels; each pass = single k-sweep with 16 u64
// accumulators live. X read twice from L1; W warp-uniform from smem.
//   Hs[row] = half( dis[row] * (X[row] @ W) )
// ---------------------------------------------------------------------------
__global__ void __launch_bounds__(128) k_gemm(const float* __restrict__ X,
                                              const float* __restrict__ W,
                                              uint2* __restrict__ H) {
    __shared__ ulonglong2 WsU[1024];          // 64x64 floats = 16KB
    float* Ws = (float*)WsU;
    int tid = threadIdx.x;
    {
        const float4* W4 = (const float4*)W;
        float4* Ws4 = (float4*)Ws;
#pragma unroll
        for (int i = 0; i < 8; ++i) Ws4[tid + i * 128] = W4[tid + i * 128];
    }
    __syncthreads();

    int row = blockIdx.x * 128 + tid;
    if (row >= N_NODES) return;

    float di = g_dis[row];
    const float4* x4 = (const float4*)(X + (size_t)row * D);

#pragma unroll 1
    for (int jp = 0; jp < 2; ++jp) {            // 32 channels per pass
        unsigned long long a[16];
#pragma unroll
        for (int j = 0; j < 16; ++j) a[j] = 0ULL;

#pragma unroll 2
        for (int k4 = 0; k4 < 16; ++k4) {
            float4 xv = x4[k4];
            float xs[4] = {xv.x, xv.y, xv.z, xv.w};
#pragma unroll
            for (int kk = 0; kk < 4; ++kk) {
                int k = k4 * 4 + kk;
                unsigned long long xb = bcast2(xs[kk]);
                const ulonglong2* wrow =
                    (const ulonglong2*)(Ws + k * D + jp * 32);
#pragma unroll
                for (int q = 0; q < 8; ++q) {
                    ulonglong2 wp = wrow[q];     // warp-uniform LDS.128
                    fma2(a[q * 2 + 0], wp.x, xb);
                    fma2(a[q * 2 + 1], wp.y, xb);
                }
            }
        }
        // store 32 channels = 8 uint2
#pragma unroll
        for (int q = 0; q < 8; ++q) {
            float2 f0 = unpack2(a[q * 2 + 0]);
            float2 f1 = unpack2(a[q * 2 + 1]);
            __half2 h0 = __floats2half2_rn(f0.x * di, f0.y * di);
            __half2 h1 = __floats2half2_rn(f1.x * di, f1.y * di);
            H[(size_t)row * 16 + jp * 8 + q] =
                make_uint2(*(unsigned*)&h0, *(unsigned*)&h1);
        }
    }
}

// ---------------------------------------------------------------------------
// CSR aggregate: 16 lanes per node; lane owns 4 channels (uint2 = 2 half2).
// fp32 accumulation; fused self-loop, dis scale, ReLU. x8 unroll (MLP=8).
// ---------------------------------------------------------------------------
__device__ __forceinline__ void acc_h4(float4& acc, uint2 v, float nm) {
    float2 f0 = __half22float2(*(__half2*)&v.x);
    float2 f1 = __half22float2(*(__half2*)&v.y);
    acc.x = fmaf(nm, f0.x, acc.x); acc.y = fmaf(nm, f0.y, acc.y);
    acc.z = fmaf(nm, f1.x, acc.z); acc.w = fmaf(nm, f1.y, acc.w);
}

__global__ void __launch_bounds__(256) k_agg(const uint2* __restrict__ H,
                                             float* __restrict__ A) {
    int idx = blockIdx.x * 256 + threadIdx.x;
    int n = idx >> 4;
    if (n >= N_NODES) return;
    int l = idx & 15;

    int e   = g_row[n];
    int end = e + g_cnt[n];

    float4 acc;
    {   // self-loop term Hs[n]
        uint2 sv = H[(size_t)n * 16 + l];
        float2 f0 = __half22float2(*(__half2*)&sv.x);
        float2 f1 = __half22float2(*(__half2*)&sv.y);
        acc = make_float4(f0.x, f0.y, f1.x, f1.y);
    }

    for (; e + 8 <= end; e += 8) {
        int2 p[8];
#pragma unroll
        for (int j = 0; j < 8; ++j) p[j] = g_bins[e + j];
        uint2 v[8];
#pragma unroll
        for (int j = 0; j < 8; ++j) v[j] = H[(size_t)p[j].x * 16 + l];
#pragma unroll
        for (int j = 0; j < 8; ++j) acc_h4(acc, v[j], __int_as_float(p[j].y));
    }
    if (e + 4 <= end) {
        int2 p[4];
#pragma unroll
        for (int j = 0; j < 4; ++j) p[j] = g_bins[e + j];
        uint2 v[4];
#pragma unroll
        for (int j = 0; j < 4; ++j) v[j] = H[(size_t)p[j].x * 16 + l];
#pragma unroll
        for (int j = 0; j < 4; ++j) acc_h4(acc, v[j], __int_as_float(p[j].y));
        e += 4;
    }
    for (; e < end; ++e) {
        int2 p = g_bins[e];
        uint2 v = H[(size_t)p.x * 16 + l];
        acc_h4(acc, v, __int_as_float(p.y));
    }

    float di = g_dis[n];
    acc.x = fmaxf(acc.x * di, 0.f); acc.y = fmaxf(acc.y * di, 0.f);
    acc.z = fmaxf(acc.z * di, 0.f); acc.w = fmaxf(acc.w * di, 0.f);
    ((float4*)A)[(size_t)n * 16 + l] = acc;
}

// ---------------------------------------------------------------------------
extern "C" void kernel_launch(void* const* d_in, const int* in_sizes, int n_in,
                              void* d_out, int out_size) {
    const float* x   = (const float*)d_in[0];
    const int*   ei  = (const int*)d_in[1];     // int32 (JAX x64 disabled)
    const float* w   = (const float*)d_in[2];
    const float* W0  = (const float*)d_in[3];
    const float* W1  = (const float*)d_in[4];
    float* out = (float*)d_out;

    const int* src = ei;
    const int* dst = ei + N_EDGES;

    uint2* p_h;
    float* p_agg;
    cudaGetSymbolAddress((void**)&p_h, g_h);
    cudaGetSymbolAddress((void**)&p_agg, g_agg);

    const int TB = 256;
    int gN    = (N_NODES + TB - 1) / TB;
    int gE4   = (N_EDGES / 4 + TB - 1) / TB;
    int gAgg  = (N_NODES * 16 + TB - 1) / TB;
    int gGemm = (N_NODES + 127) / 128;          // 1 row/thread, 128 thr

    // prep
    k_init<<<gN, TB>>>();
    k_hist<<<gE4, TB>>>(dst, w);
    k_alloc<<<gN, TB>>>();
    k_fill<<<gE4, TB>>>(src, dst, w);

    // layer 1
    k_gemm<<<gGemm, 128>>>(x, W0, p_h);
    k_agg<<<gAgg, TB>>>(p_h, p_agg);

    // layer 2
    k_gemm<<<gGemm, 128>>>(p_agg, W1, p_h);
    k_agg<<<gAgg, TB>>>(p_h, out);
}

// round 16
// speedup vs baseline: 1.3799x; 1.2025x over previous
#include <cuda_runtime.h>
#include <cuda_fp16.h>
#include <cstdint>

// GCN 2-layer, CSR two-phase aggregation, sm_100a.
// GEMM: f32x2 packed math, 2 rows/thread, FULL unroll (R11 structure),
// fp16 A-operand to cut register pressure (128->64 X regs).
// Hs fp16; agg1 emits fp16 for gemm2; prep = R11 config.

#define N_NODES 100000
#define N_EDGES 1600000
#define D 64
#define FIXS 33554432.0f          // 2^25 fixed-point scale for weight sums
#define FIXR (1.0f / 33554432.0f)

__device__ unsigned long long g_pk[N_NODES];  // (cnt << 32) | fixed_weight_sum
__device__ float g_dis[N_NODES];        // rsqrt(degree)
__device__ int   g_cnt[N_NODES];        // in-degree (edges only)
__device__ int   g_row[N_NODES];        // CSR row start (bump-allocated)
__device__ int   g_total;               // bump allocator
__device__ int   g_pos[N_EDGES];        // within-bin slot (from hist atomic)
__device__ int2  g_bins[N_EDGES];       // (src, w-as-int), dst-binned
__device__ uint2 g_xh[N_NODES * 16];    // layer-1 input as fp16
__device__ uint2 g_h[N_NODES * 16];     // Hs fp16 (gemm out / agg in)
__device__ uint2 g_hh[N_NODES * 16];    // agg1 out fp16 (gemm2 in)

// ---------------------------------------------------------------------------
// packed f32x2 helpers (sm_100+)
// ---------------------------------------------------------------------------
__device__ __forceinline__ unsigned long long bcast2(float x) {
    unsigned long long r;
    asm("mov.b64 %0, {%1, %1};" : "=l"(r) : "f"(x));
    return r;
}
__device__ __forceinline__ void fma2(unsigned long long& d,
                                     unsigned long long a,
                                     unsigned long long b) {
    asm("fma.rn.f32x2 %0, %1, %2, %0;" : "+l"(d) : "l"(a), "l"(b));
}
__device__ __forceinline__ float2 unpack2(unsigned long long v) {
    float2 f;
    asm("mov.b64 {%0, %1}, %2;" : "=f"(f.x), "=f"(f.y) : "l"(v));
    return f;
}

// ---------------------------------------------------------------------------
__global__ void k_init() {
    int i = blockIdx.x * blockDim.x + threadIdx.x;
    if (i < N_NODES) g_pk[i] = 0ULL;
    if (i == 0) g_total = 0;
}

// convert fp32 node features to fp16 once (layer-1 A operand)
__global__ void k_xcast(const float* __restrict__ X, uint2* __restrict__ XH) {
    int i = blockIdx.x * blockDim.x + threadIdx.x;
    if (i >= N_NODES * 16) return;
    float4 v = ((const float4*)X)[i];
    __half2 h0 = __floats2half2_rn(v.x, v.y);
    __half2 h1 = __floats2half2_rn(v.z, v.w);
    XH[i] = make_uint2(*(unsigned*)&h0, *(unsigned*)&h1);
}

// one packed 64-bit atomic per edge: count (hi) + fixed-point weight sum (lo)
__global__ void k_hist(const int* __restrict__ dst,
                       const float* __restrict__ w) {
    int t = blockIdx.x * blockDim.x + threadIdx.x;
    if (t >= N_EDGES / 4) return;
    int4   dv = ((const int4*)dst)[t];
    float4 wv = ((const float4*)w)[t];
    unsigned long long a0 = (1ULL << 32) | (unsigned)__float2uint_rn(wv.x * FIXS);
    unsigned long long a1 = (1ULL << 32) | (unsigned)__float2uint_rn(wv.y * FIXS);
    unsigned long long a2 = (1ULL << 32) | (unsigned)__float2uint_rn(wv.z * FIXS);
    unsigned long long a3 = (1ULL << 32) | (unsigned)__float2uint_rn(wv.w * FIXS);
    int p0 = (int)(atomicAdd(&g_pk[dv.x], a0) >> 32);
    int p1 = (int)(atomicAdd(&g_pk[dv.y], a1) >> 32);
    int p2 = (int)(atomicAdd(&g_pk[dv.z], a2) >> 32);
    int p3 = (int)(atomicAdd(&g_pk[dv.w], a3) >> 32);
    ((int4*)g_pos)[t] = make_int4(p0, p1, p2, p3);
}

__global__ void k_alloc() {
    int i = blockIdx.x * blockDim.x + threadIdx.x;
    if (i >= N_NODES) return;
    unsigned long long pk = g_pk[i];
    int cnt = (int)(pk >> 32);
    float deg = 1.0f + (float)(unsigned)(pk & 0xFFFFFFFFULL) * FIXR;
    g_dis[i] = rsqrtf(deg);
    g_cnt[i] = cnt;
    g_row[i] = atomicAdd(&g_total, cnt);
}

// fill bins: payload (src, raw w); one row[dst] gather, no dis gathers
__global__ void k_fill(const int* __restrict__ src,
                       const int* __restrict__ dst,
                       const float* __restrict__ w) {
    int t = blockIdx.x * blockDim.x + threadIdx.x;
    if (t >= N_EDGES / 4) return;
    int4   sv = ((const int4*)src)[t];
    int4   dv = ((const int4*)dst)[t];
    int4   pv = ((const int4*)g_pos)[t];
    float4 wv = ((const float4*)w)[t];
    int r0 = g_row[dv.x], r1 = g_row[dv.y], r2 = g_row[dv.z], r3 = g_row[dv.w];
    g_bins[r0 + pv.x] = make_int2(sv.x, __float_as_int(wv.x));
    g_bins[r1 + pv.y] = make_int2(sv.y, __float_as_int(wv.y));
    g_bins[r2 + pv.z] = make_int2(sv.z, __float_as_int(wv.z));
    g_bins[r3 + pv.w] = make_int2(sv.w, __float_as_int(wv.w));
}

// ---------------------------------------------------------------------------
// dense 64x64 GEMM, f32x2 packed math, 2 rows/thread, fp16 A operand.
// Full unroll (R11 structure); X footprint halved -> better occupancy.
//   Hs[row] = half( dis[row] * (Xh[row] @ W) )
// ---------------------------------------------------------------------------
__global__ void __launch_bounds__(128) k_gemm(const uint2* __restrict__ Xh,
                                              const float* __restrict__ W,
                                              uint2* __restrict__ H) {
    __shared__ ulonglong2 WsU[1024];          // 64x64 floats = 16KB
    float* Ws = (float*)WsU;
    int tid = threadIdx.x;
    {
        const float4* W4 = (const float4*)W;
        float4* Ws4 = (float4*)Ws;
#pragma unroll
        for (int i = 0; i < 8; ++i) Ws4[tid + i * 128] = W4[tid + i * 128];
    }
    __syncthreads();

    int r0 = blockIdx.x * 256 + tid;
    int r1 = r0 + 128;
    bool has1 = (r1 < N_NODES);
    if (r0 >= N_NODES) return;

    float di0 = g_dis[r0];
    float di1 = has1 ? g_dis[r1] : 0.f;

    // stage both rows' fp16 features: 32 half2 per row = 16 regs each (u32)
    unsigned xs0[32], xs1[32];
    {
        const uint4* p0 = (const uint4*)(Xh + (size_t)r0 * 16);
        const uint4* p1 = (const uint4*)(Xh + (size_t)(has1 ? r1 : r0) * 16);
#pragma unroll
        for (int i = 0; i < 8; ++i) {
            ((uint4*)xs0)[i] = p0[i];
            ((uint4*)xs1)[i] = p1[i];
        }
    }

#pragma unroll 1
    for (int jc = 0; jc < 4; ++jc) {            // 16 output channels per chunk
        unsigned long long a0[8], a1[8];
#pragma unroll
        for (int j = 0; j < 8; ++j) { a0[j] = 0ULL; a1[j] = 0ULL; }

#pragma unroll
        for (int kp = 0; kp < 32; ++kp) {       // half2 pairs: k=2kp, 2kp+1
            float2 f0 = __half22float2(*(__half2*)&xs0[kp]);
            float2 f1 = __half22float2(*(__half2*)&xs1[kp]);
            unsigned long long x00 = bcast2(f0.x), x01 = bcast2(f0.y);
            unsigned long long x10 = bcast2(f1.x), x11 = bcast2(f1.y);
            const ulonglong2* w0 =
                (const ulonglong2*)(Ws + (kp * 2 + 0) * D + jc * 16);
            const ulonglong2* w1 =
                (const ulonglong2*)(Ws + (kp * 2 + 1) * D + jc * 16);
#pragma unroll
            for (int q = 0; q < 4; ++q) {
                ulonglong2 wp0 = w0[q];
                ulonglong2 wp1 = w1[q];
                fma2(a0[q * 2 + 0], wp0.x, x00);
                fma2(a0[q * 2 + 1], wp0.y, x00);
                fma2(a1[q * 2 + 0], wp0.x, x10);
                fma2(a1[q * 2 + 1], wp0.y, x10);
                fma2(a0[q * 2 + 0], wp1.x, x01);
                fma2(a0[q * 2 + 1], wp1.y, x01);
                fma2(a1[q * 2 + 0], wp1.x, x11);
                fma2(a1[q * 2 + 1], wp1.y, x11);
            }
        }
#pragma unroll
        for (int q = 0; q < 4; ++q) {
            float2 f0 = unpack2(a0[q * 2 + 0]);
            float2 f1 = unpack2(a0[q * 2 + 1]);
            __half2 h0 = __floats2half2_rn(f0.x * di0, f0.y * di0);
            __half2 h1 = __floats2half2_rn(f1.x * di0, f1.y * di0);
            H[(size_t)r0 * 16 + jc * 4 + q] =
                make_uint2(*(unsigned*)&h0, *(unsigned*)&h1);
        }
        if (has1) {
#pragma unroll
            for (int q = 0; q < 4; ++q) {
                float2 f0 = unpack2(a1[q * 2 + 0]);
                float2 f1 = unpack2(a1[q * 2 + 1]);
                __half2 h0 = __floats2half2_rn(f0.x * di1, f0.y * di1);
                __half2 h1 = __floats2half2_rn(f1.x * di1, f1.y * di1);
                H[(size_t)r1 * 16 + jc * 4 + q] =
                    make_uint2(*(unsigned*)&h0, *(unsigned*)&h1);
            }
        }
    }
}

// ---------------------------------------------------------------------------
// CSR aggregate: 16 lanes per node; lane owns 4 channels (uint2 = 2 half2).
// fp32 accumulation; fused self-loop, dis scale, ReLU. x8 unroll (MLP=8).
// OUT16: emit fp16 (feeds gemm2); else fp32 (final output).
// ---------------------------------------------------------------------------
__device__ __forceinline__ void acc_h4(float4& acc, uint2 v, float nm) {
    float2 f0 = __half22float2(*(__half2*)&v.x);
    float2 f1 = __half22float2(*(__half2*)&v.y);
    acc.x = fmaf(nm, f0.x, acc.x); acc.y = fmaf(nm, f0.y, acc.y);
    acc.z = fmaf(nm, f1.x, acc.z); acc.w = fmaf(nm, f1.y, acc.w);
}

template <int OUT16>
__global__ void __launch_bounds__(256) k_agg(const uint2* __restrict__ H,
                                             void* __restrict__ A) {
    int idx = blockIdx.x * 256 + threadIdx.x;
    int n = idx >> 4;
    if (n >= N_NODES) return;
    int l = idx & 15;

    int e   = g_row[n];
    int end = e + g_cnt[n];

    float4 acc;
    {   // self-loop term Hs[n]
        uint2 sv = H[(size_t)n * 16 + l];
        float2 f0 = __half22float2(*(__half2*)&sv.x);
        float2 f1 = __half22float2(*(__half2*)&sv.y);
        acc = make_float4(f0.x, f0.y, f1.x, f1.y);
    }

    for (; e + 8 <= end; e += 8) {
        int2 p[8];
#pragma unroll
        for (int j = 0; j < 8; ++j) p[j] = g_bins[e + j];
        uint2 v[8];
#pragma unroll
        for (int j = 0; j < 8; ++j) v[j] = H[(size_t)p[j].x * 16 + l];
#pragma unroll
        for (int j = 0; j < 8; ++j) acc_h4(acc, v[j], __int_as_float(p[j].y));
    }
    if (e + 4 <= end) {
        int2 p[4];
#pragma unroll
        for (int j = 0; j < 4; ++j) p[j] = g_bins[e + j];
        uint2 v[4];
#pragma unroll
        for (int j = 0; j < 4; ++j) v[j] = H[(size_t)p[j].x * 16 + l];
#pragma unroll
        for (int j = 0; j < 4; ++j) acc_h4(acc, v[j], __int_as_float(p[j].y));
        e += 4;
    }
    for (; e < end; ++e) {
        int2 p = g_bins[e];
        uint2 v = H[(size_t)p.x * 16 + l];
        acc_h4(acc, v, __int_as_float(p.y));
    }

    float di = g_dis[n];
    acc.x = fmaxf(acc.x * di, 0.f); acc.y = fmaxf(acc.y * di, 0.f);
    acc.z = fmaxf(acc.z * di, 0.f); acc.w = fmaxf(acc.w * di, 0.f);
    if (OUT16) {
        __half2 h0 = __floats2half2_rn(acc.x, acc.y);
        __half2 h1 = __floats2half2_rn(acc.z, acc.w);
        ((uint2*)A)[(size_t)n * 16 + l] =
            make_uint2(*(unsigned*)&h0, *(unsigned*)&h1);
    } else {
        ((float4*)A)[(size_t)n * 16 + l] = acc;
    }
}

// ---------------------------------------------------------------------------
extern "C" void kernel_launch(void* const* d_in, const int* in_sizes, int n_in,
                              void* d_out, int out_size) {
    const float* x   = (const float*)d_in[0];
    const int*   ei  = (const int*)d_in[1];     // int32 (JAX x64 disabled)
    const float* w   = (const float*)d_in[2];
    const float* W0  = (const float*)d_in[3];
    const float* W1  = (const float*)d_in[4];
    float* out = (float*)d_out;

    const int* src = ei;
    const int* dst = ei + N_EDGES;

    uint2 *p_xh, *p_h, *p_hh;
    cudaGetSymbolAddress((void**)&p_xh, g_xh);
    cudaGetSymbolAddress((void**)&p_h, g_h);
    cudaGetSymbolAddress((void**)&p_hh, g_hh);

    const int TB = 256;
    int gN    = (N_NODES + TB - 1) / TB;
    int gE4   = (N_EDGES / 4 + TB - 1) / TB;
    int gAgg  = (N_NODES * 16 + TB - 1) / TB;
    int gGemm = (N_NODES + 255) / 256;          // 2 rows/thread, 128 thr

    // prep
    k_init<<<gN, TB>>>();
    k_xcast<<<gAgg, TB>>>(x, p_xh);
    k_hist<<<gE4, TB>>>(dst, w);
    k_alloc<<<gN, TB>>>();
    k_fill<<<gE4, TB>>>(src, dst, w);

    // layer 1 (fp16 A from xcast; agg emits fp16 for gemm2)
    k_gemm<<<gGemm, 128>>>(p_xh, W0, p_h);
    k_agg<1><<<gAgg, TB>>>(p_h, p_hh);

    // layer 2 (fp16 A from agg1; agg emits fp32 final output)
    k_gemm<<<gGemm, 128>>>(p_hh, W1, p_h);
    k_agg<0><<<gAgg, TB>>>(p_h, out);
}

// round 17
// speedup vs baseline: 1.4326x; 1.0382x over previous
#include <cuda_runtime.h>
#include <cuda_fp16.h>
#include <cstdint>

// GCN 2-layer, CSR two-phase aggregation, sm_100a.
// Dis-free GEMM (raw X@W -> fp16) runs CONCURRENT with the prep chain via
// stream-forked graph capture. dis factors live in the edge payload
// (w*dis_src) and the agg epilogue (dis_n twice). R11 kernel structures.

#define N_NODES 100000
#define N_EDGES 1600000
#define D 64
#define FIXS 33554432.0f          // 2^25 fixed-point scale for weight sums
#define FIXR (1.0f / 33554432.0f)

__device__ unsigned long long g_pk[N_NODES];  // (cnt << 32) | fixed_weight_sum
__device__ float g_dis[N_NODES];        // rsqrt(degree)
__device__ int   g_cnt[N_NODES];        // in-degree (edges only)
__device__ int   g_row[N_NODES];        // CSR row start (bump-allocated)
__device__ int   g_total;               // bump allocator
__device__ int   g_pos[N_EDGES];        // within-bin slot (from hist atomic)
__device__ int2  g_bins[N_EDGES];       // (src, (w*dis_src)-as-int), dst-binned
__device__ uint2 g_h[N_NODES * 16];     // raw H fp16: 64 half = 16 uint2/node
__device__ float g_agg[N_NODES * D];    // layer-1 output (fp32)

// ---------------------------------------------------------------------------
// packed f32x2 helpers (sm_100+)
// ---------------------------------------------------------------------------
__device__ __forceinline__ unsigned long long bcast2(float x) {
    unsigned long long r;
    asm("mov.b64 %0, {%1, %1};" : "=l"(r) : "f"(x));
    return r;
}
__device__ __forceinline__ void fma2(unsigned long long& d,
                                     unsigned long long a,
                                     unsigned long long b) {
    asm("fma.rn.f32x2 %0, %1, %2, %0;" : "+l"(d) : "l"(a), "l"(b));
}
__device__ __forceinline__ float2 unpack2(unsigned long long v) {
    float2 f;
    asm("mov.b64 {%0, %1}, %2;" : "=f"(f.x), "=f"(f.y) : "l"(v));
    return f;
}

// ---------------------------------------------------------------------------
__global__ void k_init() {
    int i = blockIdx.x * blockDim.x + threadIdx.x;
    if (i < N_NODES) g_pk[i] = 0ULL;
    if (i == 0) g_total = 0;
}

// one packed 64-bit atomic per edge: count (hi) + fixed-point weight sum (lo)
__global__ void k_hist(const int* __restrict__ dst,
                       const float* __restrict__ w) {
    int t = blockIdx.x * blockDim.x + threadIdx.x;
    if (t >= N_EDGES / 4) return;
    int4   dv = ((const int4*)dst)[t];
    float4 wv = ((const float4*)w)[t];
    unsigned long long a0 = (1ULL << 32) | (unsigned)__float2uint_rn(wv.x * FIXS);
    unsigned long long a1 = (1ULL << 32) | (unsigned)__float2uint_rn(wv.y * FIXS);
    unsigned long long a2 = (1ULL << 32) | (unsigned)__float2uint_rn(wv.z * FIXS);
    unsigned long long a3 = (1ULL << 32) | (unsigned)__float2uint_rn(wv.w * FIXS);
    int p0 = (int)(atomicAdd(&g_pk[dv.x], a0) >> 32);
    int p1 = (int)(atomicAdd(&g_pk[dv.y], a1) >> 32);
    int p2 = (int)(atomicAdd(&g_pk[dv.z], a2) >> 32);
    int p3 = (int)(atomicAdd(&g_pk[dv.w], a3) >> 32);
    ((int4*)g_pos)[t] = make_int4(p0, p1, p2, p3);
}

__global__ void k_alloc() {
    int i = blockIdx.x * blockDim.x + threadIdx.x;
    if (i >= N_NODES) return;
    unsigned long long pk = g_pk[i];
    int cnt = (int)(pk >> 32);
    float deg = 1.0f + (float)(unsigned)(pk & 0xFFFFFFFFULL) * FIXR;
    g_dis[i] = rsqrtf(deg);
    g_cnt[i] = cnt;
    g_row[i] = atomicAdd(&g_total, cnt);
}

// fill bins: payload (src, w*dis[src]); gathers: dis[src] + row[dst]
__global__ void k_fill(const int* __restrict__ src,
                       const int* __restrict__ dst,
                       const float* __restrict__ w) {
    int t = blockIdx.x * blockDim.x + threadIdx.x;
    if (t >= N_EDGES / 4) return;
    int4   sv = ((const int4*)src)[t];
    int4   dv = ((const int4*)dst)[t];
    int4   pv = ((const int4*)g_pos)[t];
    float4 wv = ((const float4*)w)[t];
    float s0 = g_dis[sv.x], s1 = g_dis[sv.y], s2 = g_dis[sv.z], s3 = g_dis[sv.w];
    int r0 = g_row[dv.x], r1 = g_row[dv.y], r2 = g_row[dv.z], r3 = g_row[dv.w];
    g_bins[r0 + pv.x] = make_int2(sv.x, __float_as_int(wv.x * s0));
    g_bins[r1 + pv.y] = make_int2(sv.y, __float_as_int(wv.y * s1));
    g_bins[r2 + pv.z] = make_int2(sv.z, __float_as_int(wv.z * s2));
    g_bins[r3 + pv.w] = make_int2(sv.w, __float_as_int(wv.w * s3));
}

// ---------------------------------------------------------------------------
// dense 64x64 GEMM, f32x2 packed math, 2 rows/thread, fp16 output, NO dis:
//   H[row] = half( X[row] @ W )   (dis applied downstream in k_agg)
// ---------------------------------------------------------------------------
__global__ void __launch_bounds__(128) k_gemm(const float* __restrict__ X,
                                              const float* __restrict__ W,
                                              uint2* __restrict__ H) {
    __shared__ ulonglong2 WsU[1024];          // 64x64 floats = 16KB
    float* Ws = (float*)WsU;
    int tid = threadIdx.x;
    {
        const float4* W4 = (const float4*)W;
        float4* Ws4 = (float4*)Ws;
#pragma unroll
        for (int i = 0; i < 8; ++i) Ws4[tid + i * 128] = W4[tid + i * 128];
    }
    __syncthreads();

    int r0 = blockIdx.x * 256 + tid;
    int r1 = r0 + 128;
    bool has1 = (r1 < N_NODES);
    if (r0 >= N_NODES) return;

    const float4* x0 = (const float4*)(X + (size_t)r0 * D);
    const float4* x1 = (const float4*)(X + (size_t)(has1 ? r1 : r0) * D);

#pragma unroll 1
    for (int jc = 0; jc < 4; ++jc) {            // 16 output channels per chunk
        unsigned long long a0[8], a1[8];
#pragma unroll
        for (int j = 0; j < 8; ++j) { a0[j] = 0ULL; a1[j] = 0ULL; }

#pragma unroll
        for (int k4 = 0; k4 < 16; ++k4) {
            float4 xv0 = x0[k4];
            float4 xv1 = x1[k4];
            float xs0[4] = {xv0.x, xv0.y, xv0.z, xv0.w};
            float xs1[4] = {xv1.x, xv1.y, xv1.z, xv1.w};
#pragma unroll
            for (int kk = 0; kk < 4; ++kk) {
                int k = k4 * 4 + kk;
                unsigned long long xb0 = bcast2(xs0[kk]);
                unsigned long long xb1 = bcast2(xs1[kk]);
                const ulonglong2* wrow =
                    (const ulonglong2*)(Ws + k * D + jc * 16);
#pragma unroll
                for (int q = 0; q < 4; ++q) {
                    ulonglong2 wp = wrow[q];     // warp-uniform LDS.128
                    fma2(a0[q * 2 + 0], wp.x, xb0);
                    fma2(a0[q * 2 + 1], wp.y, xb0);
                    fma2(a1[q * 2 + 0], wp.x, xb1);
                    fma2(a1[q * 2 + 1], wp.y, xb1);
                }
            }
        }
#pragma unroll
        for (int q = 0; q < 4; ++q) {
            float2 f0 = unpack2(a0[q * 2 + 0]);
            float2 f1 = unpack2(a0[q * 2 + 1]);
            __half2 h0 = __floats2half2_rn(f0.x, f0.y);
            __half2 h1 = __floats2half2_rn(f1.x, f1.y);
            H[(size_t)r0 * 16 + jc * 4 + q] =
                make_uint2(*(unsigned*)&h0, *(unsigned*)&h1);
        }
        if (has1) {
#pragma unroll
            for (int q = 0; q < 4; ++q) {
                float2 f0 = unpack2(a1[q * 2 + 0]);
                float2 f1 = unpack2(a1[q * 2 + 1]);
                __half2 h0 = __floats2half2_rn(f0.x, f0.y);
                __half2 h1 = __floats2half2_rn(f1.x, f1.y);
                H[(size_t)r1 * 16 + jc * 4 + q] =
                    make_uint2(*(unsigned*)&h0, *(unsigned*)&h1);
            }
        }
    }
}

// ---------------------------------------------------------------------------
// CSR aggregate: A[n] = relu( dis_n * (dis_n*H[n] + sum (w*dis_src)*H[src]) )
// 16 lanes per node; lane owns 4 channels. fp32 accumulation, x8 MLP.
// ---------------------------------------------------------------------------
__device__ __forceinline__ void acc_h4(float4& acc, uint2 v, float nm) {
    float2 f0 = __half22float2(*(__half2*)&v.x);
    float2 f1 = __half22float2(*(__half2*)&v.y);
    acc.x = fmaf(nm, f0.x, acc.x); acc.y = fmaf(nm, f0.y, acc.y);
    acc.z = fmaf(nm, f1.x, acc.z); acc.w = fmaf(nm, f1.y, acc.w);
}

__global__ void __launch_bounds__(256) k_agg(const uint2* __restrict__ H,
                                             float* __restrict__ A) {
    int idx = blockIdx.x * 256 + threadIdx.x;
    int n = idx >> 4;
    if (n >= N_NODES) return;
    int l = idx & 15;

    int e   = g_row[n];
    int end = e + g_cnt[n];
    float di = g_dis[n];

    float4 acc;
    {   // self-loop term dis_n * H[n]
        uint2 sv = H[(size_t)n * 16 + l];
        float2 f0 = __half22float2(*(__half2*)&sv.x);
        float2 f1 = __half22float2(*(__half2*)&sv.y);
        acc = make_float4(f0.x * di, f0.y * di, f1.x * di, f1.y * di);
    }

    for (; e + 8 <= end; e += 8) {
        int2 p[8];
#pragma unroll
        for (int j = 0; j < 8; ++j) p[j] = g_bins[e + j];
        uint2 v[8];
#pragma unroll
        for (int j = 0; j < 8; ++j) v[j] = H[(size_t)p[j].x * 16 + l];
#pragma unroll
        for (int j = 0; j < 8; ++j) acc_h4(acc, v[j], __int_as_float(p[j].y));
    }
    if (e + 4 <= end) {
        int2 p[4];
#pragma unroll
        for (int j = 0; j < 4; ++j) p[j] = g_bins[e + j];
        uint2 v[4];
#pragma unroll
        for (int j = 0; j < 4; ++j) v[j] = H[(size_t)p[j].x * 16 + l];
#pragma unroll
        for (int j = 0; j < 4; ++j) acc_h4(acc, v[j], __int_as_float(p[j].y));
        e += 4;
    }
    for (; e < end; ++e) {
        int2 p = g_bins[e];
        uint2 v = H[(size_t)p.x * 16 + l];
        acc_h4(acc, v, __int_as_float(p.y));
    }

    acc.x = fmaxf(acc.x * di, 0.f); acc.y = fmaxf(acc.y * di, 0.f);
    acc.z = fmaxf(acc.z * di, 0.f); acc.w = fmaxf(acc.w * di, 0.f);
    ((float4*)A)[(size_t)n * 16 + l] = acc;
}

// ---------------------------------------------------------------------------
extern "C" void kernel_launch(void* const* d_in, const int* in_sizes, int n_in,
                              void* d_out, int out_size) {
    const float* x   = (const float*)d_in[0];
    const int*   ei  = (const int*)d_in[1];     // int32 (JAX x64 disabled)
    const float* w   = (const float*)d_in[2];
    const float* W0  = (const float*)d_in[3];
    const float* W1  = (const float*)d_in[4];
    float* out = (float*)d_out;

    const int* src = ei;
    const int* dst = ei + N_EDGES;

    uint2* p_h;
    float* p_agg;
    cudaGetSymbolAddress((void**)&p_h, g_h);
    cudaGetSymbolAddress((void**)&p_agg, g_agg);

    // one-time host objects (no device memory): side stream + fork/join events
    static cudaStream_t s2 = nullptr;
    static cudaEvent_t evF = nullptr, evJ = nullptr;
    if (s2 == nullptr) {
        cudaStreamCreateWithFlags(&s2, cudaStreamNonBlocking);
        cudaEventCreateWithFlags(&evF, cudaEventDisableTiming);
        cudaEventCreateWithFlags(&evJ, cudaEventDisableTiming);
    }

    const int TB = 256;
    int gN    = (N_NODES + TB - 1) / TB;
    int gE4   = (N_EDGES / 4 + TB - 1) / TB;
    int gAgg  = (N_NODES * 16 + TB - 1) / TB;
    int gGemm = (N_NODES + 255) / 256;          // 2 rows/thread, 128 thr

    // fork: prep chain on s2, concurrent with gemm1 (no dis dependency)
    cudaEventRecord(evF, 0);
    cudaStreamWaitEvent(s2, evF, 0);

    k_init<<<gN, TB, 0, s2>>>();
    k_hist<<<gE4, TB, 0, s2>>>(dst, w);
    k_alloc<<<gN, TB, 0, s2>>>();
    k_fill<<<gE4, TB, 0, s2>>>(src, dst, w);

    k_gemm<<<gGemm, 128>>>(x, W0, p_h);         // concurrent with prep

    // join
    cudaEventRecord(evJ, s2);
    cudaStreamWaitEvent(0, evJ, 0);

    // layer 1 aggregate, then layer 2 (serial)
    k_agg<<<gAgg, TB>>>(p_h, p_agg);
    k_gemm<<<gGemm, 128>>>(p_agg, W1, p_h);
    k_agg<<<gAgg, TB>>>(p_h, out);
}